// round 8
// baseline (speedup 1.0000x reference)
#include <cuda_runtime.h>
#include <cuda_bf16.h>
#include <mma.h>
#include <math.h>
#include <stdint.h>

using namespace nvcuda;

// Problem constants
#define TT   4096
#define DM   1024
#define HH   16
#define HD   64
#define DFFc 2048
#define EE   8
#define SS   2048
#define BB   2

typedef __nv_bfloat16 bf16;

// ---------------- scratch ----------------
__device__ float g_rkv[3 * TT * DM];
__device__ float g_yf[TT * DM];
__device__ float g_yb[TT * DM];
__device__ float g_x1[TT * DM];
__device__ float g_xn2[TT * DM];
__device__ float g_moe[2 * TT * DM];
__device__ bf16  g_xn1h[TT * DM],  g_xn1l[TT * DM];
__device__ bf16  g_yah[TT * DM],   g_yal[TT * DM];
__device__ bf16  g_xn2h[TT * DM],  g_xn2l[TT * DM];
__device__ bf16  g_hh[2 * TT * DFFc], g_hl[2 * TT * DFFc];
__device__ bf16  g_wqkvh[3 * DM * DM], g_wqkvl[3 * DM * DM];
__device__ bf16  g_woh[DM * DM],   g_wol[DM * DM];
__device__ bf16  g_w1h[EE * DFFc * DM], g_w1l[EE * DFFc * DM];
__device__ bf16  g_w2h[EE * DM * DFFc], g_w2l[EE * DM * DFFc];
__device__ float g_gate[2 * TT];
__device__ int   g_list[EE * TT];
__device__ int   g_cnt[EE];
__device__ float g_pmean[EE];

__device__ __forceinline__ uint32_t smem_u32(const void* p) {
    uint32_t a;
    asm("{ .reg .u64 t; cvta.to.shared.u64 t, %1; cvt.u32.u64 %0, t; }" : "=r"(a) : "l"(p));
    return a;
}
__device__ __forceinline__ void cp_async16(uint32_t s, const void* g) {
    asm volatile("cp.async.cg.shared.global [%0], [%1], 16;" :: "r"(s), "l"(g) : "memory");
}
#define CP_COMMIT() asm volatile("cp.async.commit_group;" ::: "memory")
#define CP_WAIT1()  asm volatile("cp.async.wait_group 1;"  ::: "memory")

// ---------------- small kernels ----------------
__global__ void zero_k() {
    int i = threadIdx.x;
    if (i < EE) { g_cnt[i] = 0; g_pmean[i] = 0.f; }
}

// transpose + split: src [K,N] fp32 (batch z) -> dh/dl [N,K] bf16 (vectorized stores)
__global__ void tsplit_k(const float* __restrict__ src, bf16* __restrict__ dh,
                         bf16* __restrict__ dl, int K, int N) {
    int e = blockIdx.z;
    src += (size_t)e * K * N;
    dh  += (size_t)e * N * K;
    dl  += (size_t)e * N * K;
    __shared__ float tile[32][33];
    int n0 = blockIdx.x * 32, k0 = blockIdx.y * 32;
    int tx = threadIdx.x, ty = threadIdx.y;
#pragma unroll
    for (int i = 0; i < 4; i++)
        tile[ty + i * 8][tx] = src[(size_t)(k0 + ty + i * 8) * N + n0 + tx];
    __syncthreads();
    int t = ty * 32 + tx;
#pragma unroll
    for (int it = 0; it < 2; it++) {
        int i = t + it * 256;
        int row = i >> 4;        // n-local 0..31
        int kp  = i & 15;        // bf162 pair index
        float v0 = tile[kp * 2][row];
        float v1 = tile[kp * 2 + 1][row];
        bf16 h0 = __float2bfloat16_rn(v0);
        bf16 h1 = __float2bfloat16_rn(v1);
        __nv_bfloat162 hv; hv.x = h0; hv.y = h1;
        __nv_bfloat162 lv;
        lv.x = __float2bfloat16_rn(v0 - __bfloat162float(h0));
        lv.y = __float2bfloat16_rn(v1 - __bfloat162float(h1));
        size_t o = ((size_t)(n0 + row) * K + k0 + kp * 2) >> 1;
        ((__nv_bfloat162*)dh)[o] = hv;
        ((__nv_bfloat162*)dl)[o] = lv;
    }
}

__global__ void splitadd_k(const float* __restrict__ a, const float* __restrict__ b,
                           bf16* __restrict__ hi, bf16* __restrict__ lo, int n) {
    int i = blockIdx.x * blockDim.x + threadIdx.x;
    if (i >= n) return;
    float v = a[i] + b[i];
    bf16 h = __float2bfloat16_rn(v);
    hi[i] = h;
    lo[i] = __float2bfloat16_rn(v - __bfloat162float(h));
}

template <bool WRITE_F32>
__global__ void rmsnorm_k(const float* __restrict__ x, const float* __restrict__ w,
                          float* __restrict__ ofp, bf16* __restrict__ ohi, bf16* __restrict__ olo) {
    int t = blockIdx.x;
    const float* xr = x + (size_t)t * DM;
    float s = 0.f;
    for (int i = threadIdx.x; i < DM; i += 256) { float v = xr[i]; s += v * v; }
    for (int off = 16; off; off >>= 1) s += __shfl_xor_sync(0xffffffffu, s, off);
    __shared__ float red[8];
    int wrp = threadIdx.x >> 5, ln = threadIdx.x & 31;
    if (ln == 0) red[wrp] = s;
    __syncthreads();
    if (wrp == 0) {
        float v = (ln < 8) ? red[ln] : 0.f;
        for (int off = 4; off; off >>= 1) v += __shfl_xor_sync(0xffffffffu, v, off);
        if (ln == 0) red[0] = v;
    }
    __syncthreads();
    float scale = rsqrtf(red[0] / (float)DM + 1e-6f);
    size_t base = (size_t)t * DM;
    for (int i = threadIdx.x; i < DM; i += 256) {
        float v = xr[i] * scale * w[i];
        if (WRITE_F32) ofp[base + i] = v;
        bf16 h = __float2bfloat16_rn(v);
        ohi[base + i] = h;
        olo[base + i] = __float2bfloat16_rn(v - __bfloat162float(h));
    }
}

// ---------------- RWKV bidirectional scan (2-deep register prefetch) ----------------
__global__ void scan_k(const float* __restrict__ r, const float* __restrict__ k,
                       const float* __restrict__ v,
                       const float* __restrict__ decay, const float* __restrict__ bonus) {
    int h  = blockIdx.x >> 1;
    int vh = blockIdx.x & 1;
    int b  = blockIdx.y;
    int dir = blockIdx.z;
    int tid = threadIdx.x;
    int vcol  = vh * 32 + (tid >> 2);
    int kc    = tid & 3;
    int kbase = kc * 16;

    float Sst[16], wr_[16], ur_[16];
#pragma unroll
    for (int i = 0; i < 16; i++) {
        Sst[i] = 0.f;
        float d = decay[h * HD + kbase + i];
        wr_[i] = expf(-expf(d));
        ur_[i] = bonus[h * HD + kbase + i];
    }
    float* yo = dir ? g_yb : g_yf;

    int aoff = (tid < 64) ? tid : (tid - 64);
    const float* asrc = (tid < 64) ? r : k;

    auto sidx = [&](int s) -> size_t {
        int idx = dir ? (SS - 1 - s) : s;
        return ((size_t)(b * SS + idx)) * DM + h * HD;
    };

    __shared__ float s_r[2][64], s_k[2][64];

    float ld_a[2], ld_v[2];
    {
        size_t b0 = sidx(0), b1 = sidx(1);
        ld_a[0] = asrc[b0 + aoff]; ld_v[0] = v[b0 + vcol];
        ld_a[1] = asrc[b1 + aoff]; ld_v[1] = v[b1 + vcol];
    }

    for (int s = 0; s < SS; s++) {
        int sl = s & 1;
        if (tid < 64) s_r[sl][tid] = ld_a[sl];
        else          s_k[sl][tid - 64] = ld_a[sl];
        float vv = ld_v[sl];
        size_t obase = sidx(s);
        __syncthreads();
        if (s + 2 < SS) {
            size_t bn = sidx(s + 2);
            ld_a[sl] = asrc[bn + aoff];
            ld_v[sl] = v[bn + vcol];
        }
        float y = 0.f;
#pragma unroll
        for (int i = 0; i < 16; i++) {
            float kk  = s_k[sl][kbase + i];
            float rr  = s_r[sl][kbase + i];
            float kv  = kk * vv;
            float tmp = fmaf(ur_[i], kv, Sst[i]);
            y = fmaf(rr, tmp, y);
            Sst[i] = fmaf(wr_[i], Sst[i], kv);
        }
        y += __shfl_xor_sync(0xffffffffu, y, 1);
        y += __shfl_xor_sync(0xffffffffu, y, 2);
        if (kc == 0) yo[obase + vcol] = y;
    }
}

// ---------------- router ----------------
__global__ void router_k(const float* __restrict__ xn2, const float* __restrict__ rw) {
    int t = blockIdx.x, tid = threadIdx.x;
    __shared__ float sx[DM];
    __shared__ float slog[8];
    const float* xr = xn2 + (size_t)t * DM;
    for (int i = tid; i < DM; i += 256) sx[i] = xr[i];
    __syncthreads();
    int w = tid >> 5, l = tid & 31;
    float acc = 0.f;
    for (int d = l; d < DM; d += 32) acc = fmaf(sx[d], rw[d * EE + w], acc);
    for (int off = 16; off; off >>= 1) acc += __shfl_xor_sync(0xffffffffu, acc, off);
    if (l == 0) slog[w] = acc;
    __syncthreads();
    if (tid == 0) {
        float mx = -1e30f;
        for (int e = 0; e < EE; e++) mx = fmaxf(mx, slog[e]);
        float p[EE], sum = 0.f;
        for (int e = 0; e < EE; e++) { p[e] = expf(slog[e] - mx); sum += p[e]; }
        float inv = 1.f / sum;
        int e0 = 0; float b0 = -1.f;
        for (int e = 0; e < EE; e++) { p[e] *= inv; if (p[e] > b0) { b0 = p[e]; e0 = e; } }
        int e1 = -1; float b1 = -1.f;
        for (int e = 0; e < EE; e++) { if (e == e0) continue; if (p[e] > b1) { b1 = p[e]; e1 = e; } }
        float gs = 1.f / (b0 + b1);
        g_gate[2 * t]     = b0 * gs;
        g_gate[2 * t + 1] = b1 * gs;
        int pos0 = atomicAdd(&g_cnt[e0], 1); g_list[e0 * TT + pos0] = 2 * t;
        int pos1 = atomicAdd(&g_cnt[e1], 1); g_list[e1 * TT + pos1] = 2 * t + 1;
        for (int e = 0; e < EE; e++) atomicAdd(&g_pmean[e], p[e]);
    }
}

// ---------------- WMMA bf16 split GEMM, 2-stage cp.async (R6 mainloop) ----------------
// CTA tile BMT x 256, BK=32, 8 warps (2M x 4N), warp tile (BMT/2) x 64.
// D = Ah*Bh + Ah*Bl + Al*Bh   (fp32 accumulate)
// MODE 0 = QKV (z 0..2), 1 = WO (+resid), 2 = MoE up (gather, silu -> hi/lo),
// MODE 3 = MoE down (gather, *gate -> fp32)
#define BNw 256
#define BKw 32
#define LDT 40
#define B_TYPE_B  (256 * LDT * 2)          // 20480 bytes
#define CLD 260                            // epilogue fp32 ld (64*260*4 = 66560 B)

template <int BMT> struct GCfg {
    static constexpr int ATB   = BMT * LDT * 2;
    static constexpr int STAGE = 2 * ATB + 2 * B_TYPE_B;
    static constexpr int SMEM  = 2 * STAGE;
};

template <int MODE, int BMT>
__global__ void __launch_bounds__(256, 1)
wgemm_k(const bf16* __restrict__ Ah, const bf16* __restrict__ Al,
        const bf16* __restrict__ Bh, const bf16* __restrict__ Bl,
        const float* __restrict__ resid, float* __restrict__ Cf,
        bf16* __restrict__ Chh, bf16* __restrict__ Chl,
        int M, int N, int K) {
    constexpr int MI   = BMT / 32;
    constexpr int AITS = BMT / 64;
    constexpr int ATB  = GCfg<BMT>::ATB;
    constexpr int STG  = GCfg<BMT>::STAGE;
    constexpr int NPASS = BMT / 64;

    int z = blockIdx.z;
    int bx = blockIdx.x, by = blockIdx.y;
    int Mrows = M;
    const int* list = nullptr;
    if (MODE == 2 || MODE == 3) { Mrows = g_cnt[z]; list = g_list + z * TT; }
    if (by * BMT >= Mrows) return;

    size_t boff = 0;
    if (MODE == 0) boff = (size_t)z * DM * DM;
    if (MODE == 2) boff = (size_t)z * DFFc * DM;
    if (MODE == 3) boff = (size_t)z * DM * DFFc;
    const bf16* bhg = Bh + boff;
    const bf16* blg = Bl + boff;
    float* cf = Cf;
    if (MODE == 0) cf = Cf + (size_t)z * TT * DM;

    extern __shared__ char smem[];
    uint32_t sb = smem_u32(smem);

    int tid = threadIdx.x;
    int wid = tid >> 5;
    int wm = wid & 1;
    int wn = wid >> 1;

    size_t a_src[AITS]; uint32_t a_so[AITS];
#pragma unroll
    for (int it = 0; it < AITS; it++) {
        int idx = tid + it * 256;
        int row = idx >> 2, seg = idx & 3;
        int ar = by * BMT + row;
        if (MODE == 2 || MODE == 3) {
            int rc = ar < Mrows ? ar : (Mrows - 1);
            int p = list[rc];
            ar = (MODE == 2) ? (p >> 1) : p;
        }
        a_src[it] = (size_t)ar * K + seg * 8;
        a_so[it] = (uint32_t)((row * LDT + seg * 8) * 2);
    }
    size_t b_src[4]; uint32_t b_so[4];
#pragma unroll
    for (int it = 0; it < 4; it++) {
        int idx = tid + it * 256;
        int row = idx >> 2, seg = idx & 3;
        b_src[it] = (size_t)(bx * BNw + row) * K + seg * 8;
        b_so[it] = (uint32_t)((row * LDT + seg * 8) * 2);
    }

    const int NC = K / BKw;
    auto issue = [&](int ci, int buf) {
        if (ci < NC) {
            int k0 = ci * BKw;
            uint32_t base = sb + buf * STG;
#pragma unroll
            for (int it = 0; it < AITS; it++) {
                cp_async16(base + a_so[it],       Ah + a_src[it] + k0);
                cp_async16(base + ATB + a_so[it], Al + a_src[it] + k0);
            }
#pragma unroll
            for (int it = 0; it < 4; it++) {
                cp_async16(base + 2 * ATB + b_so[it],            bhg + b_src[it] + k0);
                cp_async16(base + 2 * ATB + B_TYPE_B + b_so[it], blg + b_src[it] + k0);
            }
        }
        CP_COMMIT();
    };

    wmma::fragment<wmma::accumulator, 16, 16, 16, float> c[MI][4];
#pragma unroll
    for (int mi = 0; mi < MI; mi++)
#pragma unroll
        for (int ni = 0; ni < 4; ni++) wmma::fill_fragment(c[mi][ni], 0.f);

    issue(0, 0);
    issue(1, 1);

    for (int i = 0; i < NC; i++) {
        CP_WAIT1();
        __syncthreads();
        int buf = i & 1;
        const bf16* sAh = (const bf16*)(smem + buf * STG);
        const bf16* sAl = (const bf16*)(smem + buf * STG + ATB);
        const bf16* sBh = (const bf16*)(smem + buf * STG + 2 * ATB);
        const bf16* sBl = (const bf16*)(smem + buf * STG + 2 * ATB + B_TYPE_B);
#pragma unroll
        for (int kk = 0; kk < 2; kk++) {
            wmma::fragment<wmma::matrix_a, 16, 16, 16, bf16, wmma::row_major> ah[MI], al[MI];
#pragma unroll
            for (int mi = 0; mi < MI; mi++) {
                wmma::load_matrix_sync(ah[mi], sAh + (wm * (BMT / 2) + mi * 16) * LDT + kk * 16, LDT);
                wmma::load_matrix_sync(al[mi], sAl + (wm * (BMT / 2) + mi * 16) * LDT + kk * 16, LDT);
            }
#pragma unroll
            for (int ni = 0; ni < 4; ni++) {
                wmma::fragment<wmma::matrix_b, 16, 16, 16, bf16, wmma::col_major> bhf, blf;
                wmma::load_matrix_sync(bhf, sBh + (wn * 64 + ni * 16) * LDT + kk * 16, LDT);
                wmma::load_matrix_sync(blf, sBl + (wn * 64 + ni * 16) * LDT + kk * 16, LDT);
#pragma unroll
                for (int mi = 0; mi < MI; mi++) {
                    wmma::mma_sync(c[mi][ni], ah[mi], bhf, c[mi][ni]);
                    wmma::mma_sync(c[mi][ni], ah[mi], blf, c[mi][ni]);
                    wmma::mma_sync(c[mi][ni], al[mi], bhf, c[mi][ni]);
                }
            }
        }
        __syncthreads();
        issue(i + 2, buf);
    }

    // ---- epilogue: NPASS 64-row passes through smem ----
    float* sC = (float*)smem;
    int lrow = tid >> 2;
    int cseg = (tid & 3) * 64;
#pragma unroll
    for (int pass = 0; pass < NPASS; pass++) {
        __syncthreads();
        if ((wm * (BMT / 2)) / 64 == pass) {
            int rbase = (wm * (BMT / 2)) % 64;
#pragma unroll
            for (int mi = 0; mi < MI; mi++)
#pragma unroll
                for (int ni = 0; ni < 4; ni++)
                    wmma::store_matrix_sync(sC + (rbase + mi * 16) * CLD + wn * 64 + ni * 16,
                                            c[mi][ni], CLD, wmma::mem_row_major);
        }
        __syncthreads();
        int arow = by * BMT + pass * 64 + lrow;
        if (arow >= Mrows) continue;
        const float* src = sC + lrow * CLD + cseg;
        int colb = bx * BNw + cseg;
        if (MODE == 2) {
            int p = list[arow];
            size_t ro = (size_t)p * DFFc + colb;
#pragma unroll
            for (int j = 0; j < 32; j++) {
                float v0 = src[2 * j], v1 = src[2 * j + 1];
                v0 = v0 / (1.f + expf(-v0));
                v1 = v1 / (1.f + expf(-v1));
                bf16 h0 = __float2bfloat16_rn(v0);
                bf16 h1 = __float2bfloat16_rn(v1);
                __nv_bfloat162 hv; hv.x = h0; hv.y = h1;
                __nv_bfloat162 lv;
                lv.x = __float2bfloat16_rn(v0 - __bfloat162float(h0));
                lv.y = __float2bfloat16_rn(v1 - __bfloat162float(h1));
                *((__nv_bfloat162*)(Chh + ro) + j) = hv;
                *((__nv_bfloat162*)(Chl + ro) + j) = lv;
            }
        } else if (MODE == 3) {
            int p = list[arow];
            float gate = g_gate[p];
            size_t ro = (size_t)p * DM + colb;
#pragma unroll
            for (int j = 0; j < 16; j++) {
                float4 v = *(const float4*)(src + 4 * j);
                v.x *= gate; v.y *= gate; v.z *= gate; v.w *= gate;
                *(float4*)(Cf + ro + 4 * j) = v;
            }
        } else {
            size_t ro = (size_t)arow * N + colb;
#pragma unroll
            for (int j = 0; j < 16; j++) {
                float4 v = *(const float4*)(src + 4 * j);
                if (MODE == 1) {
                    float4 rs = *(const float4*)(resid + ro + 4 * j);
                    v.x += rs.x; v.y += rs.y; v.z += rs.z; v.w += rs.w;
                }
                *(float4*)(cf + ro + 4 * j) = v;
            }
        }
    }
}

// ---------------- finalize ----------------
__global__ void finalize_k(float* __restrict__ out, int out_size) {
    int t = blockIdx.x;
    for (int i = threadIdx.x; i < DM; i += 256) {
        size_t o = (size_t)t * DM + i;
        out[o] = g_x1[o] + g_moe[(size_t)(2 * t) * DM + i] + g_moe[(size_t)(2 * t + 1) * DM + i];
    }
    if (blockIdx.x == 0 && threadIdx.x == 0 && out_size > TT * DM) {
        float aux = 0.f;
        for (int e = 0; e < EE; e++)
            aux += ((float)g_cnt[e] / (float)(TT * 2)) * (g_pmean[e] / (float)TT);
        out[out_size - 1] = aux * (float)EE;
    }
}

// ---------------- host launcher ----------------
extern "C" void kernel_launch(void* const* d_in, const int* in_sizes, int n_in,
                              void* d_out, int out_size) {
    const float* x     = (const float*)d_in[0];
    const float* n1w   = (const float*)d_in[2];
    const float* n2w   = (const float*)d_in[3];
    const float* Wr    = (const float*)d_in[4];
    const float* Wk    = (const float*)d_in[5];
    const float* Wv    = (const float*)d_in[6];
    const float* Wo    = (const float*)d_in[7];
    const float* decay = (const float*)d_in[8];
    const float* bonus = (const float*)d_in[9];
    const float* rw    = (const float*)d_in[10];
    const float* w1    = (const float*)d_in[11];
    const float* w2    = (const float*)d_in[12];
    float* out = (float*)d_out;

    float *rkv, *yf, *yb, *x1, *xn2, *moe;
    bf16 *xn1h, *xn1l, *yah, *yal, *xn2h, *xn2l, *hh, *hl;
    bf16 *wqkvh, *wqkvl, *woh, *wol, *w1h, *w1l, *w2h, *w2l;
    cudaGetSymbolAddress((void**)&rkv,  g_rkv);
    cudaGetSymbolAddress((void**)&yf,   g_yf);
    cudaGetSymbolAddress((void**)&yb,   g_yb);
    cudaGetSymbolAddress((void**)&x1,   g_x1);
    cudaGetSymbolAddress((void**)&xn2,  g_xn2);
    cudaGetSymbolAddress((void**)&moe,  g_moe);
    cudaGetSymbolAddress((void**)&xn1h, g_xn1h);
    cudaGetSymbolAddress((void**)&xn1l, g_xn1l);
    cudaGetSymbolAddress((void**)&yah,  g_yah);
    cudaGetSymbolAddress((void**)&yal,  g_yal);
    cudaGetSymbolAddress((void**)&xn2h, g_xn2h);
    cudaGetSymbolAddress((void**)&xn2l, g_xn2l);
    cudaGetSymbolAddress((void**)&hh,   g_hh);
    cudaGetSymbolAddress((void**)&hl,   g_hl);
    cudaGetSymbolAddress((void**)&wqkvh, g_wqkvh);
    cudaGetSymbolAddress((void**)&wqkvl, g_wqkvl);
    cudaGetSymbolAddress((void**)&woh,  g_woh);
    cudaGetSymbolAddress((void**)&wol,  g_wol);
    cudaGetSymbolAddress((void**)&w1h,  g_w1h);
    cudaGetSymbolAddress((void**)&w1l,  g_w1l);
    cudaGetSymbolAddress((void**)&w2h,  g_w2h);
    cudaGetSymbolAddress((void**)&w2l,  g_w2l);

    cudaFuncSetAttribute(wgemm_k<0, 128>, cudaFuncAttributeMaxDynamicSharedMemorySize, GCfg<128>::SMEM);
    cudaFuncSetAttribute(wgemm_k<1, 64>,  cudaFuncAttributeMaxDynamicSharedMemorySize, GCfg<64>::SMEM);
    cudaFuncSetAttribute(wgemm_k<2, 128>, cudaFuncAttributeMaxDynamicSharedMemorySize, GCfg<128>::SMEM);
    cudaFuncSetAttribute(wgemm_k<3, 128>, cudaFuncAttributeMaxDynamicSharedMemorySize, GCfg<128>::SMEM);

    zero_k<<<1, 32>>>();

    dim3 tb(32, 8);
    tsplit_k<<<dim3(DM / 32, DM / 32, 1), tb>>>(Wr, wqkvh,               wqkvl,               DM, DM);
    tsplit_k<<<dim3(DM / 32, DM / 32, 1), tb>>>(Wk, wqkvh + DM * DM,     wqkvl + DM * DM,     DM, DM);
    tsplit_k<<<dim3(DM / 32, DM / 32, 1), tb>>>(Wv, wqkvh + 2 * DM * DM, wqkvl + 2 * DM * DM, DM, DM);
    tsplit_k<<<dim3(DM / 32, DM / 32, 1), tb>>>(Wo, woh, wol, DM, DM);
    tsplit_k<<<dim3(DFFc / 32, DM / 32, EE), tb>>>(w1, w1h, w1l, DM, DFFc);
    tsplit_k<<<dim3(DM / 32, DFFc / 32, EE), tb>>>(w2, w2h, w2l, DFFc, DM);

    rmsnorm_k<false><<<TT, 256>>>(x, n1w, nullptr, xn1h, xn1l);

    // QKV
    wgemm_k<0, 128><<<dim3(DM / BNw, TT / 128, 3), 256, GCfg<128>::SMEM>>>(
        xn1h, xn1l, wqkvh, wqkvl, nullptr, rkv, nullptr, nullptr, TT, DM, DM);

    scan_k<<<dim3(HH * 2, BB, 2), 128>>>(rkv, rkv + TT * DM, rkv + 2 * TT * DM, decay, bonus);

    splitadd_k<<<(TT * DM + 255) / 256, 256>>>(yf, yb, yah, yal, TT * DM);

    // x1 = x + (yf+yb) @ Wo  — BMT=64 for full-chip occupancy (256 CTAs)
    wgemm_k<1, 64><<<dim3(DM / BNw, TT / 64, 1), 256, GCfg<64>::SMEM>>>(
        yah, yal, woh, wol, x, x1, nullptr, nullptr, TT, DM, DM);

    rmsnorm_k<true><<<TT, 256>>>(x1, n2w, xn2, xn2h, xn2l);
    router_k<<<TT, 256>>>(xn2, rw);

    // MoE up
    wgemm_k<2, 128><<<dim3(DFFc / BNw, TT / 128, EE), 256, GCfg<128>::SMEM>>>(
        xn2h, xn2l, w1h, w1l, nullptr, nullptr, hh, hl, 0, DFFc, DM);
    // MoE down
    wgemm_k<3, 128><<<dim3(DM / BNw, TT / 128, EE), 256, GCfg<128>::SMEM>>>(
        hh, hl, w2h, w2l, nullptr, moe, nullptr, nullptr, 0, DM, DFFc);

    finalize_k<<<TT, 256>>>(out, out_size);
}

// round 9
// speedup vs baseline: 1.0958x; 1.0958x over previous
#include <cuda_runtime.h>
#include <cuda_bf16.h>
#include <mma.h>
#include <math.h>
#include <stdint.h>

using namespace nvcuda;

// Problem constants
#define TT   4096
#define DM   1024
#define HH   16
#define HD   64
#define DFFc 2048
#define EE   8
#define SS   2048
#define BB   2

typedef __nv_bfloat16 bf16;

// ---------------- scratch ----------------
__device__ float g_rkv[3 * TT * DM];
__device__ float g_yf[TT * DM];
__device__ float g_yb[TT * DM];
__device__ float g_x1[TT * DM];
__device__ float g_xn2[TT * DM];
__device__ float g_moe[2 * TT * DM];
__device__ bf16  g_xn1h[TT * DM],  g_xn1l[TT * DM];
__device__ bf16  g_yah[TT * DM],   g_yal[TT * DM];
__device__ bf16  g_xn2h[TT * DM],  g_xn2l[TT * DM];
__device__ bf16  g_hh[2 * TT * DFFc], g_hl[2 * TT * DFFc];
__device__ bf16  g_wqkvh[3 * DM * DM], g_wqkvl[3 * DM * DM];
__device__ bf16  g_woh[DM * DM],   g_wol[DM * DM];
__device__ bf16  g_w1h[EE * DFFc * DM], g_w1l[EE * DFFc * DM];
__device__ bf16  g_w2h[EE * DM * DFFc], g_w2l[EE * DM * DFFc];
__device__ float g_gate[2 * TT];
__device__ int   g_list[EE * TT];
__device__ int   g_cnt[EE];
__device__ float g_pmean[EE];

__device__ __forceinline__ uint32_t smem_u32(const void* p) {
    uint32_t a;
    asm("{ .reg .u64 t; cvta.to.shared.u64 t, %1; cvt.u32.u64 %0, t; }" : "=r"(a) : "l"(p));
    return a;
}
__device__ __forceinline__ void cp_async16(uint32_t s, const void* g) {
    asm volatile("cp.async.cg.shared.global [%0], [%1], 16;" :: "r"(s), "l"(g) : "memory");
}
#define CP_COMMIT() asm volatile("cp.async.commit_group;" ::: "memory")
#define CP_WAIT1()  asm volatile("cp.async.wait_group 1;"  ::: "memory")

// ---------------- small kernels ----------------
__global__ void zero_k() {
    int i = threadIdx.x;
    if (i < EE) { g_cnt[i] = 0; g_pmean[i] = 0.f; }
}

// transpose + split: src [K,N] fp32 (batch z) -> dh/dl [N,K] bf16 (vectorized stores)
__global__ void tsplit_k(const float* __restrict__ src, bf16* __restrict__ dh,
                         bf16* __restrict__ dl, int K, int N) {
    int e = blockIdx.z;
    src += (size_t)e * K * N;
    dh  += (size_t)e * N * K;
    dl  += (size_t)e * N * K;
    __shared__ float tile[32][33];
    int n0 = blockIdx.x * 32, k0 = blockIdx.y * 32;
    int tx = threadIdx.x, ty = threadIdx.y;
#pragma unroll
    for (int i = 0; i < 4; i++)
        tile[ty + i * 8][tx] = src[(size_t)(k0 + ty + i * 8) * N + n0 + tx];
    __syncthreads();
    int t = ty * 32 + tx;
#pragma unroll
    for (int it = 0; it < 2; it++) {
        int i = t + it * 256;
        int row = i >> 4;        // n-local 0..31
        int kp  = i & 15;        // bf162 pair index
        float v0 = tile[kp * 2][row];
        float v1 = tile[kp * 2 + 1][row];
        bf16 h0 = __float2bfloat16_rn(v0);
        bf16 h1 = __float2bfloat16_rn(v1);
        __nv_bfloat162 hv; hv.x = h0; hv.y = h1;
        __nv_bfloat162 lv;
        lv.x = __float2bfloat16_rn(v0 - __bfloat162float(h0));
        lv.y = __float2bfloat16_rn(v1 - __bfloat162float(h1));
        size_t o = ((size_t)(n0 + row) * K + k0 + kp * 2) >> 1;
        ((__nv_bfloat162*)dh)[o] = hv;
        ((__nv_bfloat162*)dl)[o] = lv;
    }
}

__global__ void splitadd_k(const float* __restrict__ a, const float* __restrict__ b,
                           bf16* __restrict__ hi, bf16* __restrict__ lo, int n) {
    int i = blockIdx.x * blockDim.x + threadIdx.x;
    if (i >= n) return;
    float v = a[i] + b[i];
    bf16 h = __float2bfloat16_rn(v);
    hi[i] = h;
    lo[i] = __float2bfloat16_rn(v - __bfloat162float(h));
}

template <bool WRITE_F32>
__global__ void rmsnorm_k(const float* __restrict__ x, const float* __restrict__ w,
                          float* __restrict__ ofp, bf16* __restrict__ ohi, bf16* __restrict__ olo) {
    int t = blockIdx.x;
    const float* xr = x + (size_t)t * DM;
    float s = 0.f;
    for (int i = threadIdx.x; i < DM; i += 256) { float v = xr[i]; s += v * v; }
    for (int off = 16; off; off >>= 1) s += __shfl_xor_sync(0xffffffffu, s, off);
    __shared__ float red[8];
    int wrp = threadIdx.x >> 5, ln = threadIdx.x & 31;
    if (ln == 0) red[wrp] = s;
    __syncthreads();
    if (wrp == 0) {
        float v = (ln < 8) ? red[ln] : 0.f;
        for (int off = 4; off; off >>= 1) v += __shfl_xor_sync(0xffffffffu, v, off);
        if (ln == 0) red[0] = v;
    }
    __syncthreads();
    float scale = rsqrtf(red[0] / (float)DM + 1e-6f);
    size_t base = (size_t)t * DM;
    for (int i = threadIdx.x; i < DM; i += 256) {
        float v = xr[i] * scale * w[i];
        if (WRITE_F32) ofp[base + i] = v;
        bf16 h = __float2bfloat16_rn(v);
        ohi[base + i] = h;
        olo[base + i] = __float2bfloat16_rn(v - __bfloat162float(h));
    }
}

// ---------------- RWKV bidirectional scan (R6 version) ----------------
__global__ void scan_k(const float* __restrict__ r, const float* __restrict__ k,
                       const float* __restrict__ v,
                       const float* __restrict__ decay, const float* __restrict__ bonus) {
    int h  = blockIdx.x >> 1;
    int vh = blockIdx.x & 1;
    int b  = blockIdx.y;
    int dir = blockIdx.z;
    int tid = threadIdx.x;
    int vcol  = vh * 32 + (tid >> 2);
    int kc    = tid & 3;
    int kbase = kc * 16;

    float Sst[16], wr_[16], ur_[16];
#pragma unroll
    for (int i = 0; i < 16; i++) {
        Sst[i] = 0.f;
        float d = decay[h * HD + kbase + i];
        wr_[i] = expf(-expf(d));
        ur_[i] = bonus[h * HD + kbase + i];
    }
    float* yo = dir ? g_yb : g_yf;

    __shared__ float s_r[2][64], s_k[2][64];
    for (int s = 0; s < SS; s++) {
        int idx = dir ? (SS - 1 - s) : s;
        size_t base = ((size_t)(b * SS + idx)) * DM + h * HD;
        int bf = s & 1;
        if (tid < 64)       s_r[bf][tid]      = r[base + tid];
        else                s_k[bf][tid - 64] = k[base + tid - 64];
        float vv = v[base + vcol];
        __syncthreads();
        float y = 0.f;
#pragma unroll
        for (int i = 0; i < 16; i++) {
            float kk  = s_k[bf][kbase + i];
            float rr  = s_r[bf][kbase + i];
            float kv  = kk * vv;
            float tmp = fmaf(ur_[i], kv, Sst[i]);
            y = fmaf(rr, tmp, y);
            Sst[i] = fmaf(wr_[i], Sst[i], kv);
        }
        y += __shfl_xor_sync(0xffffffffu, y, 1);
        y += __shfl_xor_sync(0xffffffffu, y, 2);
        if (kc == 0) yo[base + vcol] = y;
    }
}

// ---------------- router ----------------
__global__ void router_k(const float* __restrict__ xn2, const float* __restrict__ rw) {
    int t = blockIdx.x, tid = threadIdx.x;
    __shared__ float sx[DM];
    __shared__ float slog[8];
    const float* xr = xn2 + (size_t)t * DM;
    for (int i = tid; i < DM; i += 256) sx[i] = xr[i];
    __syncthreads();
    int w = tid >> 5, l = tid & 31;
    float acc = 0.f;
    for (int d = l; d < DM; d += 32) acc = fmaf(sx[d], rw[d * EE + w], acc);
    for (int off = 16; off; off >>= 1) acc += __shfl_xor_sync(0xffffffffu, acc, off);
    if (l == 0) slog[w] = acc;
    __syncthreads();
    if (tid == 0) {
        float mx = -1e30f;
        for (int e = 0; e < EE; e++) mx = fmaxf(mx, slog[e]);
        float p[EE], sum = 0.f;
        for (int e = 0; e < EE; e++) { p[e] = expf(slog[e] - mx); sum += p[e]; }
        float inv = 1.f / sum;
        int e0 = 0; float b0 = -1.f;
        for (int e = 0; e < EE; e++) { p[e] *= inv; if (p[e] > b0) { b0 = p[e]; e0 = e; } }
        int e1 = -1; float b1 = -1.f;
        for (int e = 0; e < EE; e++) { if (e == e0) continue; if (p[e] > b1) { b1 = p[e]; e1 = e; } }
        float gs = 1.f / (b0 + b1);
        g_gate[2 * t]     = b0 * gs;
        g_gate[2 * t + 1] = b1 * gs;
        int pos0 = atomicAdd(&g_cnt[e0], 1); g_list[e0 * TT + pos0] = 2 * t;
        int pos1 = atomicAdd(&g_cnt[e1], 1); g_list[e1 * TT + pos1] = 2 * t + 1;
        for (int e = 0; e < EE; e++) atomicAdd(&g_pmean[e], p[e]);
    }
}

// ---------------- WMMA bf16 split GEMM, 2-stage cp.async (R6 mainloop) ----------------
// CTA tile BMT x 256, BK=32, 8 warps (2M x 4N), warp tile (BMT/2) x 64.
// D = Ah*Bh + Ah*Bl + Al*Bh   (fp32 accumulate)
// MODE 0 = QKV (z 0..2), 1 = WO (+resid), 2 = MoE up (gather, silu -> hi/lo),
// MODE 3 = MoE down (gather, *gate -> fp32)
#define BNw 256
#define BKw 32
#define LDT 40
#define B_TYPE_B  (256 * LDT * 2)          // 20480 bytes
#define CLD 260                            // epilogue fp32 ld (64*260*4 = 66560 B)

template <int BMT> struct GCfg {
    static constexpr int ATB   = BMT * LDT * 2;
    static constexpr int STAGE = 2 * ATB + 2 * B_TYPE_B;
    static constexpr int SMEM  = 2 * STAGE;
};

template <int MODE, int BMT>
__global__ void __launch_bounds__(256, 1)
wgemm_k(const bf16* __restrict__ Ah, const bf16* __restrict__ Al,
        const bf16* __restrict__ Bh, const bf16* __restrict__ Bl,
        const float* __restrict__ resid, float* __restrict__ Cf,
        bf16* __restrict__ Chh, bf16* __restrict__ Chl,
        int M, int N, int K) {
    constexpr int MI   = BMT / 32;
    constexpr int AITS = BMT / 64;
    constexpr int ATB  = GCfg<BMT>::ATB;
    constexpr int STG  = GCfg<BMT>::STAGE;
    constexpr int NPASS = BMT / 64;

    int z = blockIdx.z;
    int bx = blockIdx.x, by = blockIdx.y;
    int Mrows = M;
    const int* list = nullptr;
    if (MODE == 2 || MODE == 3) { Mrows = g_cnt[z]; list = g_list + z * TT; }
    if (by * BMT >= Mrows) return;

    size_t boff = 0;
    if (MODE == 0) boff = (size_t)z * DM * DM;
    if (MODE == 2) boff = (size_t)z * DFFc * DM;
    if (MODE == 3) boff = (size_t)z * DM * DFFc;
    const bf16* bhg = Bh + boff;
    const bf16* blg = Bl + boff;
    float* cf = Cf;
    if (MODE == 0) cf = Cf + (size_t)z * TT * DM;

    extern __shared__ char smem[];
    uint32_t sb = smem_u32(smem);

    int tid = threadIdx.x;
    int wid = tid >> 5;
    int wm = wid & 1;
    int wn = wid >> 1;

    size_t a_src[AITS]; uint32_t a_so[AITS];
#pragma unroll
    for (int it = 0; it < AITS; it++) {
        int idx = tid + it * 256;
        int row = idx >> 2, seg = idx & 3;
        int ar = by * BMT + row;
        if (MODE == 2 || MODE == 3) {
            int rc = ar < Mrows ? ar : (Mrows - 1);
            int p = list[rc];
            ar = (MODE == 2) ? (p >> 1) : p;
        }
        a_src[it] = (size_t)ar * K + seg * 8;
        a_so[it] = (uint32_t)((row * LDT + seg * 8) * 2);
    }
    size_t b_src[4]; uint32_t b_so[4];
#pragma unroll
    for (int it = 0; it < 4; it++) {
        int idx = tid + it * 256;
        int row = idx >> 2, seg = idx & 3;
        b_src[it] = (size_t)(bx * BNw + row) * K + seg * 8;
        b_so[it] = (uint32_t)((row * LDT + seg * 8) * 2);
    }

    const int NC = K / BKw;
    auto issue = [&](int ci, int buf) {
        if (ci < NC) {
            int k0 = ci * BKw;
            uint32_t base = sb + buf * STG;
#pragma unroll
            for (int it = 0; it < AITS; it++) {
                cp_async16(base + a_so[it],       Ah + a_src[it] + k0);
                cp_async16(base + ATB + a_so[it], Al + a_src[it] + k0);
            }
#pragma unroll
            for (int it = 0; it < 4; it++) {
                cp_async16(base + 2 * ATB + b_so[it],            bhg + b_src[it] + k0);
                cp_async16(base + 2 * ATB + B_TYPE_B + b_so[it], blg + b_src[it] + k0);
            }
        }
        CP_COMMIT();
    };

    wmma::fragment<wmma::accumulator, 16, 16, 16, float> c[MI][4];
#pragma unroll
    for (int mi = 0; mi < MI; mi++)
#pragma unroll
        for (int ni = 0; ni < 4; ni++) wmma::fill_fragment(c[mi][ni], 0.f);

    issue(0, 0);
    issue(1, 1);

    for (int i = 0; i < NC; i++) {
        CP_WAIT1();
        __syncthreads();
        int buf = i & 1;
        const bf16* sAh = (const bf16*)(smem + buf * STG);
        const bf16* sAl = (const bf16*)(smem + buf * STG + ATB);
        const bf16* sBh = (const bf16*)(smem + buf * STG + 2 * ATB);
        const bf16* sBl = (const bf16*)(smem + buf * STG + 2 * ATB + B_TYPE_B);
#pragma unroll
        for (int kk = 0; kk < 2; kk++) {
            wmma::fragment<wmma::matrix_a, 16, 16, 16, bf16, wmma::row_major> ah[MI], al[MI];
#pragma unroll
            for (int mi = 0; mi < MI; mi++) {
                wmma::load_matrix_sync(ah[mi], sAh + (wm * (BMT / 2) + mi * 16) * LDT + kk * 16, LDT);
                wmma::load_matrix_sync(al[mi], sAl + (wm * (BMT / 2) + mi * 16) * LDT + kk * 16, LDT);
            }
#pragma unroll
            for (int ni = 0; ni < 4; ni++) {
                wmma::fragment<wmma::matrix_b, 16, 16, 16, bf16, wmma::col_major> bhf, blf;
                wmma::load_matrix_sync(bhf, sBh + (wn * 64 + ni * 16) * LDT + kk * 16, LDT);
                wmma::load_matrix_sync(blf, sBl + (wn * 64 + ni * 16) * LDT + kk * 16, LDT);
#pragma unroll
                for (int mi = 0; mi < MI; mi++) {
                    wmma::mma_sync(c[mi][ni], ah[mi], bhf, c[mi][ni]);
                    wmma::mma_sync(c[mi][ni], ah[mi], blf, c[mi][ni]);
                    wmma::mma_sync(c[mi][ni], al[mi], bhf, c[mi][ni]);
                }
            }
        }
        __syncthreads();
        issue(i + 2, buf);
    }

    // ---- epilogue: NPASS 64-row passes through smem ----
    float* sC = (float*)smem;
    int lrow = tid >> 2;
    int cseg = (tid & 3) * 64;
#pragma unroll
    for (int pass = 0; pass < NPASS; pass++) {
        __syncthreads();
        if ((wm * (BMT / 2)) / 64 == pass) {
            int rbase = (wm * (BMT / 2)) % 64;
#pragma unroll
            for (int mi = 0; mi < MI; mi++)
#pragma unroll
                for (int ni = 0; ni < 4; ni++)
                    wmma::store_matrix_sync(sC + (rbase + mi * 16) * CLD + wn * 64 + ni * 16,
                                            c[mi][ni], CLD, wmma::mem_row_major);
        }
        __syncthreads();
        int arow = by * BMT + pass * 64 + lrow;
        if (arow >= Mrows) continue;
        const float* src = sC + lrow * CLD + cseg;
        int colb = bx * BNw + cseg;
        if (MODE == 2) {
            int p = list[arow];
            size_t ro = (size_t)p * DFFc + colb;
#pragma unroll
            for (int j = 0; j < 32; j++) {
                float v0 = src[2 * j], v1 = src[2 * j + 1];
                v0 = v0 / (1.f + expf(-v0));
                v1 = v1 / (1.f + expf(-v1));
                bf16 h0 = __float2bfloat16_rn(v0);
                bf16 h1 = __float2bfloat16_rn(v1);
                __nv_bfloat162 hv; hv.x = h0; hv.y = h1;
                __nv_bfloat162 lv;
                lv.x = __float2bfloat16_rn(v0 - __bfloat162float(h0));
                lv.y = __float2bfloat16_rn(v1 - __bfloat162float(h1));
                *((__nv_bfloat162*)(Chh + ro) + j) = hv;
                *((__nv_bfloat162*)(Chl + ro) + j) = lv;
            }
        } else if (MODE == 3) {
            int p = list[arow];
            float gate = g_gate[p];
            size_t ro = (size_t)p * DM + colb;
#pragma unroll
            for (int j = 0; j < 16; j++) {
                float4 v = *(const float4*)(src + 4 * j);
                v.x *= gate; v.y *= gate; v.z *= gate; v.w *= gate;
                *(float4*)(Cf + ro + 4 * j) = v;
            }
        } else {
            size_t ro = (size_t)arow * N + colb;
#pragma unroll
            for (int j = 0; j < 16; j++) {
                float4 v = *(const float4*)(src + 4 * j);
                if (MODE == 1) {
                    float4 rs = *(const float4*)(resid + ro + 4 * j);
                    v.x += rs.x; v.y += rs.y; v.z += rs.z; v.w += rs.w;
                }
                *(float4*)(cf + ro + 4 * j) = v;
            }
        }
    }
}

// ---------------- finalize ----------------
__global__ void finalize_k(float* __restrict__ out, int out_size) {
    int t = blockIdx.x;
    for (int i = threadIdx.x; i < DM; i += 256) {
        size_t o = (size_t)t * DM + i;
        out[o] = g_x1[o] + g_moe[(size_t)(2 * t) * DM + i] + g_moe[(size_t)(2 * t + 1) * DM + i];
    }
    if (blockIdx.x == 0 && threadIdx.x == 0 && out_size > TT * DM) {
        float aux = 0.f;
        for (int e = 0; e < EE; e++)
            aux += ((float)g_cnt[e] / (float)(TT * 2)) * (g_pmean[e] / (float)TT);
        out[out_size - 1] = aux * (float)EE;
    }
}

// ---------------- host launcher ----------------
extern "C" void kernel_launch(void* const* d_in, const int* in_sizes, int n_in,
                              void* d_out, int out_size) {
    const float* x     = (const float*)d_in[0];
    const float* n1w   = (const float*)d_in[2];
    const float* n2w   = (const float*)d_in[3];
    const float* Wr    = (const float*)d_in[4];
    const float* Wk    = (const float*)d_in[5];
    const float* Wv    = (const float*)d_in[6];
    const float* Wo    = (const float*)d_in[7];
    const float* decay = (const float*)d_in[8];
    const float* bonus = (const float*)d_in[9];
    const float* rw    = (const float*)d_in[10];
    const float* w1    = (const float*)d_in[11];
    const float* w2    = (const float*)d_in[12];
    float* out = (float*)d_out;

    float *rkv, *yf, *yb, *x1, *xn2, *moe;
    bf16 *xn1h, *xn1l, *yah, *yal, *xn2h, *xn2l, *hh, *hl;
    bf16 *wqkvh, *wqkvl, *woh, *wol, *w1h, *w1l, *w2h, *w2l;
    cudaGetSymbolAddress((void**)&rkv,  g_rkv);
    cudaGetSymbolAddress((void**)&yf,   g_yf);
    cudaGetSymbolAddress((void**)&yb,   g_yb);
    cudaGetSymbolAddress((void**)&x1,   g_x1);
    cudaGetSymbolAddress((void**)&xn2,  g_xn2);
    cudaGetSymbolAddress((void**)&moe,  g_moe);
    cudaGetSymbolAddress((void**)&xn1h, g_xn1h);
    cudaGetSymbolAddress((void**)&xn1l, g_xn1l);
    cudaGetSymbolAddress((void**)&yah,  g_yah);
    cudaGetSymbolAddress((void**)&yal,  g_yal);
    cudaGetSymbolAddress((void**)&xn2h, g_xn2h);
    cudaGetSymbolAddress((void**)&xn2l, g_xn2l);
    cudaGetSymbolAddress((void**)&hh,   g_hh);
    cudaGetSymbolAddress((void**)&hl,   g_hl);
    cudaGetSymbolAddress((void**)&wqkvh, g_wqkvh);
    cudaGetSymbolAddress((void**)&wqkvl, g_wqkvl);
    cudaGetSymbolAddress((void**)&woh,  g_woh);
    cudaGetSymbolAddress((void**)&wol,  g_wol);
    cudaGetSymbolAddress((void**)&w1h,  g_w1h);
    cudaGetSymbolAddress((void**)&w1l,  g_w1l);
    cudaGetSymbolAddress((void**)&w2h,  g_w2h);
    cudaGetSymbolAddress((void**)&w2l,  g_w2l);

    cudaFuncSetAttribute(wgemm_k<0, 128>, cudaFuncAttributeMaxDynamicSharedMemorySize, GCfg<128>::SMEM);
    cudaFuncSetAttribute(wgemm_k<1, 64>,  cudaFuncAttributeMaxDynamicSharedMemorySize, GCfg<64>::SMEM);
    cudaFuncSetAttribute(wgemm_k<2, 128>, cudaFuncAttributeMaxDynamicSharedMemorySize, GCfg<128>::SMEM);
    cudaFuncSetAttribute(wgemm_k<3, 128>, cudaFuncAttributeMaxDynamicSharedMemorySize, GCfg<128>::SMEM);

    zero_k<<<1, 32>>>();

    dim3 tb(32, 8);
    tsplit_k<<<dim3(DM / 32, DM / 32, 1), tb>>>(Wr, wqkvh,               wqkvl,               DM, DM);
    tsplit_k<<<dim3(DM / 32, DM / 32, 1), tb>>>(Wk, wqkvh + DM * DM,     wqkvl + DM * DM,     DM, DM);
    tsplit_k<<<dim3(DM / 32, DM / 32, 1), tb>>>(Wv, wqkvh + 2 * DM * DM, wqkvl + 2 * DM * DM, DM, DM);
    tsplit_k<<<dim3(DM / 32, DM / 32, 1), tb>>>(Wo, woh, wol, DM, DM);
    tsplit_k<<<dim3(DFFc / 32, DM / 32, EE), tb>>>(w1, w1h, w1l, DM, DFFc);
    tsplit_k<<<dim3(DM / 32, DFFc / 32, EE), tb>>>(w2, w2h, w2l, DFFc, DM);

    rmsnorm_k<false><<<TT, 256>>>(x, n1w, nullptr, xn1h, xn1l);

    // QKV
    wgemm_k<0, 128><<<dim3(DM / BNw, TT / 128, 3), 256, GCfg<128>::SMEM>>>(
        xn1h, xn1l, wqkvh, wqkvl, nullptr, rkv, nullptr, nullptr, TT, DM, DM);

    scan_k<<<dim3(HH * 2, BB, 2), 128>>>(rkv, rkv + TT * DM, rkv + 2 * TT * DM, decay, bonus);

    splitadd_k<<<(TT * DM + 255) / 256, 256>>>(yf, yb, yah, yal, TT * DM);

    // x1 = x + (yf+yb) @ Wo  — BMT=64 for full-chip occupancy (256 CTAs)
    wgemm_k<1, 64><<<dim3(DM / BNw, TT / 64, 1), 256, GCfg<64>::SMEM>>>(
        yah, yal, woh, wol, x, x1, nullptr, nullptr, TT, DM, DM);

    rmsnorm_k<true><<<TT, 256>>>(x1, n2w, xn2, xn2h, xn2l);
    router_k<<<TT, 256>>>(xn2, rw);

    // MoE up
    wgemm_k<2, 128><<<dim3(DFFc / BNw, TT / 128, EE), 256, GCfg<128>::SMEM>>>(
        xn2h, xn2l, w1h, w1l, nullptr, nullptr, hh, hl, 0, DFFc, DM);
    // MoE down
    wgemm_k<3, 128><<<dim3(DM / BNw, TT / 128, EE), 256, GCfg<128>::SMEM>>>(
        hh, hl, w2h, w2l, nullptr, moe, nullptr, nullptr, 0, DM, DFFc);

    finalize_k<<<TT, 256>>>(out, out_size);
}

// round 10
// speedup vs baseline: 1.1386x; 1.0391x over previous
#include <cuda_runtime.h>
#include <cuda_bf16.h>
#include <mma.h>
#include <math.h>
#include <stdint.h>

using namespace nvcuda;

// Problem constants
#define TT   4096
#define DM   1024
#define HH   16
#define HD   64
#define DFFc 2048
#define EE   8
#define SS   2048
#define BB   2

typedef __nv_bfloat16 bf16;

// ---------------- scratch ----------------
__device__ float g_rkv[3 * TT * DM];
__device__ float g_yf[TT * DM];
__device__ float g_yb[TT * DM];
__device__ float g_x1[TT * DM];
__device__ float g_xn2[TT * DM];
__device__ float g_moe[2 * TT * DM];
__device__ bf16  g_xn1h[TT * DM],  g_xn1l[TT * DM];
__device__ bf16  g_yah[TT * DM],   g_yal[TT * DM];
__device__ bf16  g_xn2h[TT * DM],  g_xn2l[TT * DM];
__device__ bf16  g_hh[2 * TT * DFFc], g_hl[2 * TT * DFFc];
__device__ bf16  g_wqkvh[3 * DM * DM], g_wqkvl[3 * DM * DM];
__device__ bf16  g_woh[DM * DM],   g_wol[DM * DM];
__device__ bf16  g_w1h[EE * DFFc * DM], g_w1l[EE * DFFc * DM];
__device__ bf16  g_w2h[EE * DM * DFFc], g_w2l[EE * DM * DFFc];
__device__ float g_gate[2 * TT];
__device__ int   g_list[EE * TT];
__device__ int   g_cnt[EE];
__device__ float g_pmean[EE];

__device__ __forceinline__ uint32_t smem_u32(const void* p) {
    uint32_t a;
    asm("{ .reg .u64 t; cvta.to.shared.u64 t, %1; cvt.u32.u64 %0, t; }" : "=r"(a) : "l"(p));
    return a;
}
__device__ __forceinline__ void cp_async16(uint32_t s, const void* g) {
    asm volatile("cp.async.cg.shared.global [%0], [%1], 16;" :: "r"(s), "l"(g) : "memory");
}
#define CP_COMMIT() asm volatile("cp.async.commit_group;" ::: "memory")
#define CP_WAIT1()  asm volatile("cp.async.wait_group 1;"  ::: "memory")

// ---------------- small kernels ----------------
__global__ void zero_k() {
    int i = threadIdx.x;
    if (i < EE) { g_cnt[i] = 0; g_pmean[i] = 0.f; }
}

// transpose + split: src [K,N] fp32 (batch z) -> dh/dl [N,K] bf16 (vectorized stores)
__global__ void tsplit_k(const float* __restrict__ src, bf16* __restrict__ dh,
                         bf16* __restrict__ dl, int K, int N) {
    int e = blockIdx.z;
    src += (size_t)e * K * N;
    dh  += (size_t)e * N * K;
    dl  += (size_t)e * N * K;
    __shared__ float tile[32][33];
    int n0 = blockIdx.x * 32, k0 = blockIdx.y * 32;
    int tx = threadIdx.x, ty = threadIdx.y;
#pragma unroll
    for (int i = 0; i < 4; i++)
        tile[ty + i * 8][tx] = src[(size_t)(k0 + ty + i * 8) * N + n0 + tx];
    __syncthreads();
    int t = ty * 32 + tx;
#pragma unroll
    for (int it = 0; it < 2; it++) {
        int i = t + it * 256;
        int row = i >> 4;
        int kp  = i & 15;
        float v0 = tile[kp * 2][row];
        float v1 = tile[kp * 2 + 1][row];
        bf16 h0 = __float2bfloat16_rn(v0);
        bf16 h1 = __float2bfloat16_rn(v1);
        __nv_bfloat162 hv; hv.x = h0; hv.y = h1;
        __nv_bfloat162 lv;
        lv.x = __float2bfloat16_rn(v0 - __bfloat162float(h0));
        lv.y = __float2bfloat16_rn(v1 - __bfloat162float(h1));
        size_t o = ((size_t)(n0 + row) * K + k0 + kp * 2) >> 1;
        ((__nv_bfloat162*)dh)[o] = hv;
        ((__nv_bfloat162*)dl)[o] = lv;
    }
}

__global__ void splitadd_k(const float* __restrict__ a, const float* __restrict__ b,
                           bf16* __restrict__ hi, bf16* __restrict__ lo, int n) {
    int i = blockIdx.x * blockDim.x + threadIdx.x;
    if (i >= n) return;
    float v = a[i] + b[i];
    bf16 h = __float2bfloat16_rn(v);
    hi[i] = h;
    lo[i] = __float2bfloat16_rn(v - __bfloat162float(h));
}

template <bool WRITE_F32>
__global__ void rmsnorm_k(const float* __restrict__ x, const float* __restrict__ w,
                          float* __restrict__ ofp, bf16* __restrict__ ohi, bf16* __restrict__ olo) {
    int t = blockIdx.x;
    const float* xr = x + (size_t)t * DM;
    float s = 0.f;
    for (int i = threadIdx.x; i < DM; i += 256) { float v = xr[i]; s += v * v; }
    for (int off = 16; off; off >>= 1) s += __shfl_xor_sync(0xffffffffu, s, off);
    __shared__ float red[8];
    int wrp = threadIdx.x >> 5, ln = threadIdx.x & 31;
    if (ln == 0) red[wrp] = s;
    __syncthreads();
    if (wrp == 0) {
        float v = (ln < 8) ? red[ln] : 0.f;
        for (int off = 4; off; off >>= 1) v += __shfl_xor_sync(0xffffffffu, v, off);
        if (ln == 0) red[0] = v;
    }
    __syncthreads();
    float scale = rsqrtf(red[0] / (float)DM + 1e-6f);
    size_t base = (size_t)t * DM;
    for (int i = threadIdx.x; i < DM; i += 256) {
        float v = xr[i] * scale * w[i];
        if (WRITE_F32) ofp[base + i] = v;
        bf16 h = __float2bfloat16_rn(v);
        ohi[base + i] = h;
        olo[base + i] = __float2bfloat16_rn(v - __bfloat162float(h));
    }
}

// ---------------- RWKV bidirectional scan (R6 version) ----------------
__global__ void scan_k(const float* __restrict__ r, const float* __restrict__ k,
                       const float* __restrict__ v,
                       const float* __restrict__ decay, const float* __restrict__ bonus) {
    int h  = blockIdx.x >> 1;
    int vh = blockIdx.x & 1;
    int b  = blockIdx.y;
    int dir = blockIdx.z;
    int tid = threadIdx.x;
    int vcol  = vh * 32 + (tid >> 2);
    int kc    = tid & 3;
    int kbase = kc * 16;

    float Sst[16], wr_[16], ur_[16];
#pragma unroll
    for (int i = 0; i < 16; i++) {
        Sst[i] = 0.f;
        float d = decay[h * HD + kbase + i];
        wr_[i] = expf(-expf(d));
        ur_[i] = bonus[h * HD + kbase + i];
    }
    float* yo = dir ? g_yb : g_yf;

    __shared__ float s_r[2][64], s_k[2][64];
    for (int s = 0; s < SS; s++) {
        int idx = dir ? (SS - 1 - s) : s;
        size_t base = ((size_t)(b * SS + idx)) * DM + h * HD;
        int bf = s & 1;
        if (tid < 64)       s_r[bf][tid]      = r[base + tid];
        else                s_k[bf][tid - 64] = k[base + tid - 64];
        float vv = v[base + vcol];
        __syncthreads();
        float y = 0.f;
#pragma unroll
        for (int i = 0; i < 16; i++) {
            float kk  = s_k[bf][kbase + i];
            float rr  = s_r[bf][kbase + i];
            float kv  = kk * vv;
            float tmp = fmaf(ur_[i], kv, Sst[i]);
            y = fmaf(rr, tmp, y);
            Sst[i] = fmaf(wr_[i], Sst[i], kv);
        }
        y += __shfl_xor_sync(0xffffffffu, y, 1);
        y += __shfl_xor_sync(0xffffffffu, y, 2);
        if (kc == 0) yo[base + vcol] = y;
    }
}

// ---------------- router ----------------
__global__ void router_k(const float* __restrict__ xn2, const float* __restrict__ rw) {
    int t = blockIdx.x, tid = threadIdx.x;
    __shared__ float sx[DM];
    __shared__ float slog[8];
    const float* xr = xn2 + (size_t)t * DM;
    for (int i = tid; i < DM; i += 256) sx[i] = xr[i];
    __syncthreads();
    int w = tid >> 5, l = tid & 31;
    float acc = 0.f;
    for (int d = l; d < DM; d += 32) acc = fmaf(sx[d], rw[d * EE + w], acc);
    for (int off = 16; off; off >>= 1) acc += __shfl_xor_sync(0xffffffffu, acc, off);
    if (l == 0) slog[w] = acc;
    __syncthreads();
    if (tid == 0) {
        float mx = -1e30f;
        for (int e = 0; e < EE; e++) mx = fmaxf(mx, slog[e]);
        float p[EE], sum = 0.f;
        for (int e = 0; e < EE; e++) { p[e] = expf(slog[e] - mx); sum += p[e]; }
        float inv = 1.f / sum;
        int e0 = 0; float b0 = -1.f;
        for (int e = 0; e < EE; e++) { p[e] *= inv; if (p[e] > b0) { b0 = p[e]; e0 = e; } }
        int e1 = -1; float b1 = -1.f;
        for (int e = 0; e < EE; e++) { if (e == e0) continue; if (p[e] > b1) { b1 = p[e]; e1 = e; } }
        float gs = 1.f / (b0 + b1);
        g_gate[2 * t]     = b0 * gs;
        g_gate[2 * t + 1] = b1 * gs;
        int pos0 = atomicAdd(&g_cnt[e0], 1); g_list[e0 * TT + pos0] = 2 * t;
        int pos1 = atomicAdd(&g_cnt[e1], 1); g_list[e1 * TT + pos1] = 2 * t + 1;
        for (int e = 0; e < EE; e++) atomicAdd(&g_pmean[e], p[e]);
    }
}

// ---------------- WMMA bf16 split GEMM, 2-stage cp.async, BK=64 ----------------
// CTA tile BMT x 256, BK=64, 8 warps (2M x 4N), warp tile (BMT/2) x 64.
// D = Ah*Bh + Ah*Bl + Al*Bh   (fp32 accumulate)
#define BNw 256
#define BKw 64
#define LDT 72
#define B_TYPE_B  (256 * LDT * 2)          // 36864 bytes
#define CLD 260                            // epilogue fp32 ld

template <int BMT> struct GCfg {
    static constexpr int ATB   = BMT * LDT * 2;
    static constexpr int STAGE = 2 * ATB + 2 * B_TYPE_B;
    static constexpr int SMEM  = 2 * STAGE;
};

template <int MODE, int BMT>
__global__ void __launch_bounds__(256, 1)
wgemm_k(const bf16* __restrict__ Ah, const bf16* __restrict__ Al,
        const bf16* __restrict__ Bh, const bf16* __restrict__ Bl,
        const float* __restrict__ resid, float* __restrict__ Cf,
        bf16* __restrict__ Chh, bf16* __restrict__ Chl,
        int M, int N, int K) {
    constexpr int MI   = BMT / 32;
    constexpr int AITS = BMT / 32;      // BMT rows * 8 segs / 256 threads
    constexpr int ATB  = GCfg<BMT>::ATB;
    constexpr int STG  = GCfg<BMT>::STAGE;
    constexpr int NPASS = BMT / 64;

    int z = blockIdx.z;
    int bx = blockIdx.x, by = blockIdx.y;
    int Mrows = M;
    const int* list = nullptr;
    if (MODE == 2 || MODE == 3) { Mrows = g_cnt[z]; list = g_list + z * TT; }
    if (by * BMT >= Mrows) return;

    size_t boff = 0;
    if (MODE == 0) boff = (size_t)z * DM * DM;
    if (MODE == 2) boff = (size_t)z * DFFc * DM;
    if (MODE == 3) boff = (size_t)z * DM * DFFc;
    const bf16* bhg = Bh + boff;
    const bf16* blg = Bl + boff;
    float* cf = Cf;
    if (MODE == 0) cf = Cf + (size_t)z * TT * DM;

    extern __shared__ char smem[];
    uint32_t sb = smem_u32(smem);

    int tid = threadIdx.x;
    int wid = tid >> 5;
    int wm = wid & 1;
    int wn = wid >> 1;

    // 8 segs of 16B per 64-elem row chunk
    size_t a_src[AITS]; uint32_t a_so[AITS];
#pragma unroll
    for (int it = 0; it < AITS; it++) {
        int idx = tid + it * 256;
        int row = idx >> 3, seg = idx & 7;
        int ar = by * BMT + row;
        if (MODE == 2 || MODE == 3) {
            int rc = ar < Mrows ? ar : (Mrows - 1);
            int p = list[rc];
            ar = (MODE == 2) ? (p >> 1) : p;
        }
        a_src[it] = (size_t)ar * K + seg * 8;
        a_so[it] = (uint32_t)((row * LDT + seg * 8) * 2);
    }
    size_t b_src[8]; uint32_t b_so[8];
#pragma unroll
    for (int it = 0; it < 8; it++) {
        int idx = tid + it * 256;
        int row = idx >> 3, seg = idx & 7;
        b_src[it] = (size_t)(bx * BNw + row) * K + seg * 8;
        b_so[it] = (uint32_t)((row * LDT + seg * 8) * 2);
    }

    const int NC = K / BKw;
    auto issue = [&](int ci, int buf) {
        if (ci < NC) {
            int k0 = ci * BKw;
            uint32_t base = sb + buf * STG;
#pragma unroll
            for (int it = 0; it < AITS; it++) {
                cp_async16(base + a_so[it],       Ah + a_src[it] + k0);
                cp_async16(base + ATB + a_so[it], Al + a_src[it] + k0);
            }
#pragma unroll
            for (int it = 0; it < 8; it++) {
                cp_async16(base + 2 * ATB + b_so[it],            bhg + b_src[it] + k0);
                cp_async16(base + 2 * ATB + B_TYPE_B + b_so[it], blg + b_src[it] + k0);
            }
        }
        CP_COMMIT();
    };

    wmma::fragment<wmma::accumulator, 16, 16, 16, float> c[MI][4];
#pragma unroll
    for (int mi = 0; mi < MI; mi++)
#pragma unroll
        for (int ni = 0; ni < 4; ni++) wmma::fill_fragment(c[mi][ni], 0.f);

    issue(0, 0);
    issue(1, 1);

    for (int i = 0; i < NC; i++) {
        CP_WAIT1();
        __syncthreads();
        int buf = i & 1;
        const bf16* sAh = (const bf16*)(smem + buf * STG);
        const bf16* sAl = (const bf16*)(smem + buf * STG + ATB);
        const bf16* sBh = (const bf16*)(smem + buf * STG + 2 * ATB);
        const bf16* sBl = (const bf16*)(smem + buf * STG + 2 * ATB + B_TYPE_B);
#pragma unroll
        for (int kk = 0; kk < 4; kk++) {
            wmma::fragment<wmma::matrix_a, 16, 16, 16, bf16, wmma::row_major> ah[MI], al[MI];
#pragma unroll
            for (int mi = 0; mi < MI; mi++) {
                wmma::load_matrix_sync(ah[mi], sAh + (wm * (BMT / 2) + mi * 16) * LDT + kk * 16, LDT);
                wmma::load_matrix_sync(al[mi], sAl + (wm * (BMT / 2) + mi * 16) * LDT + kk * 16, LDT);
            }
#pragma unroll
            for (int ni = 0; ni < 4; ni++) {
                wmma::fragment<wmma::matrix_b, 16, 16, 16, bf16, wmma::col_major> bhf, blf;
                wmma::load_matrix_sync(bhf, sBh + (wn * 64 + ni * 16) * LDT + kk * 16, LDT);
                wmma::load_matrix_sync(blf, sBl + (wn * 64 + ni * 16) * LDT + kk * 16, LDT);
#pragma unroll
                for (int mi = 0; mi < MI; mi++) {
                    wmma::mma_sync(c[mi][ni], ah[mi], bhf, c[mi][ni]);
                    wmma::mma_sync(c[mi][ni], ah[mi], blf, c[mi][ni]);
                    wmma::mma_sync(c[mi][ni], al[mi], bhf, c[mi][ni]);
                }
            }
        }
        __syncthreads();
        issue(i + 2, buf);
    }

    // ---- epilogue: NPASS 64-row passes through smem ----
    float* sC = (float*)smem;
    int lrow = tid >> 2;
    int cseg = (tid & 3) * 64;
#pragma unroll
    for (int pass = 0; pass < NPASS; pass++) {
        __syncthreads();
        if ((wm * (BMT / 2)) / 64 == pass) {
            int rbase = (wm * (BMT / 2)) % 64;
#pragma unroll
            for (int mi = 0; mi < MI; mi++)
#pragma unroll
                for (int ni = 0; ni < 4; ni++)
                    wmma::store_matrix_sync(sC + (rbase + mi * 16) * CLD + wn * 64 + ni * 16,
                                            c[mi][ni], CLD, wmma::mem_row_major);
        }
        __syncthreads();
        int arow = by * BMT + pass * 64 + lrow;
        if (arow >= Mrows) continue;
        const float* src = sC + lrow * CLD + cseg;
        int colb = bx * BNw + cseg;
        if (MODE == 2) {
            int p = list[arow];
            size_t ro = (size_t)p * DFFc + colb;
#pragma unroll
            for (int j = 0; j < 32; j++) {
                float v0 = src[2 * j], v1 = src[2 * j + 1];
                v0 = v0 / (1.f + expf(-v0));
                v1 = v1 / (1.f + expf(-v1));
                bf16 h0 = __float2bfloat16_rn(v0);
                bf16 h1 = __float2bfloat16_rn(v1);
                __nv_bfloat162 hv; hv.x = h0; hv.y = h1;
                __nv_bfloat162 lv;
                lv.x = __float2bfloat16_rn(v0 - __bfloat162float(h0));
                lv.y = __float2bfloat16_rn(v1 - __bfloat162float(h1));
                *((__nv_bfloat162*)(Chh + ro) + j) = hv;
                *((__nv_bfloat162*)(Chl + ro) + j) = lv;
            }
        } else if (MODE == 3) {
            int p = list[arow];
            float gate = g_gate[p];
            size_t ro = (size_t)p * DM + colb;
#pragma unroll
            for (int j = 0; j < 16; j++) {
                float4 v = *(const float4*)(src + 4 * j);
                v.x *= gate; v.y *= gate; v.z *= gate; v.w *= gate;
                *(float4*)(Cf + ro + 4 * j) = v;
            }
        } else {
            size_t ro = (size_t)arow * N + colb;
#pragma unroll
            for (int j = 0; j < 16; j++) {
                float4 v = *(const float4*)(src + 4 * j);
                if (MODE == 1) {
                    float4 rs = *(const float4*)(resid + ro + 4 * j);
                    v.x += rs.x; v.y += rs.y; v.z += rs.z; v.w += rs.w;
                }
                *(float4*)(cf + ro + 4 * j) = v;
            }
        }
    }
}

// ---------------- finalize ----------------
__global__ void finalize_k(float* __restrict__ out, int out_size) {
    int t = blockIdx.x;
    for (int i = threadIdx.x; i < DM; i += 256) {
        size_t o = (size_t)t * DM + i;
        out[o] = g_x1[o] + g_moe[(size_t)(2 * t) * DM + i] + g_moe[(size_t)(2 * t + 1) * DM + i];
    }
    if (blockIdx.x == 0 && threadIdx.x == 0 && out_size > TT * DM) {
        float aux = 0.f;
        for (int e = 0; e < EE; e++)
            aux += ((float)g_cnt[e] / (float)(TT * 2)) * (g_pmean[e] / (float)TT);
        out[out_size - 1] = aux * (float)EE;
    }
}

// ---------------- host launcher ----------------
extern "C" void kernel_launch(void* const* d_in, const int* in_sizes, int n_in,
                              void* d_out, int out_size) {
    const float* x     = (const float*)d_in[0];
    const float* n1w   = (const float*)d_in[2];
    const float* n2w   = (const float*)d_in[3];
    const float* Wr    = (const float*)d_in[4];
    const float* Wk    = (const float*)d_in[5];
    const float* Wv    = (const float*)d_in[6];
    const float* Wo    = (const float*)d_in[7];
    const float* decay = (const float*)d_in[8];
    const float* bonus = (const float*)d_in[9];
    const float* rw    = (const float*)d_in[10];
    const float* w1    = (const float*)d_in[11];
    const float* w2    = (const float*)d_in[12];
    float* out = (float*)d_out;

    float *rkv, *yf, *yb, *x1, *xn2, *moe;
    bf16 *xn1h, *xn1l, *yah, *yal, *xn2h, *xn2l, *hh, *hl;
    bf16 *wqkvh, *wqkvl, *woh, *wol, *w1h, *w1l, *w2h, *w2l;
    cudaGetSymbolAddress((void**)&rkv,  g_rkv);
    cudaGetSymbolAddress((void**)&yf,   g_yf);
    cudaGetSymbolAddress((void**)&yb,   g_yb);
    cudaGetSymbolAddress((void**)&x1,   g_x1);
    cudaGetSymbolAddress((void**)&xn2,  g_xn2);
    cudaGetSymbolAddress((void**)&moe,  g_moe);
    cudaGetSymbolAddress((void**)&xn1h, g_xn1h);
    cudaGetSymbolAddress((void**)&xn1l, g_xn1l);
    cudaGetSymbolAddress((void**)&yah,  g_yah);
    cudaGetSymbolAddress((void**)&yal,  g_yal);
    cudaGetSymbolAddress((void**)&xn2h, g_xn2h);
    cudaGetSymbolAddress((void**)&xn2l, g_xn2l);
    cudaGetSymbolAddress((void**)&hh,   g_hh);
    cudaGetSymbolAddress((void**)&hl,   g_hl);
    cudaGetSymbolAddress((void**)&wqkvh, g_wqkvh);
    cudaGetSymbolAddress((void**)&wqkvl, g_wqkvl);
    cudaGetSymbolAddress((void**)&woh,  g_woh);
    cudaGetSymbolAddress((void**)&wol,  g_wol);
    cudaGetSymbolAddress((void**)&w1h,  g_w1h);
    cudaGetSymbolAddress((void**)&w1l,  g_w1l);
    cudaGetSymbolAddress((void**)&w2h,  g_w2h);
    cudaGetSymbolAddress((void**)&w2l,  g_w2l);

    cudaFuncSetAttribute(wgemm_k<0, 128>, cudaFuncAttributeMaxDynamicSharedMemorySize, GCfg<128>::SMEM);
    cudaFuncSetAttribute(wgemm_k<1, 64>,  cudaFuncAttributeMaxDynamicSharedMemorySize, GCfg<64>::SMEM);
    cudaFuncSetAttribute(wgemm_k<2, 128>, cudaFuncAttributeMaxDynamicSharedMemorySize, GCfg<128>::SMEM);
    cudaFuncSetAttribute(wgemm_k<3, 128>, cudaFuncAttributeMaxDynamicSharedMemorySize, GCfg<128>::SMEM);

    // Launch order: QKV GEMM is the 6th launch so the fixed ncu window
    // (-s 5 -c 1) captures it instead of a tsplit.
    zero_k<<<1, 32>>>();                                                   // 1

    dim3 tb(32, 8);
    tsplit_k<<<dim3(DM / 32, DM / 32, 1), tb>>>(Wr, wqkvh,               wqkvl,               DM, DM); // 2
    tsplit_k<<<dim3(DM / 32, DM / 32, 1), tb>>>(Wk, wqkvh + DM * DM,     wqkvl + DM * DM,     DM, DM); // 3
    tsplit_k<<<dim3(DM / 32, DM / 32, 1), tb>>>(Wv, wqkvh + 2 * DM * DM, wqkvl + 2 * DM * DM, DM, DM); // 4

    rmsnorm_k<false><<<TT, 256>>>(x, n1w, nullptr, xn1h, xn1l);            // 5

    // QKV — 6th launch (profiled)
    wgemm_k<0, 128><<<dim3(DM / BNw, TT / 128, 3), 256, GCfg<128>::SMEM>>>(
        xn1h, xn1l, wqkvh, wqkvl, nullptr, rkv, nullptr, nullptr, TT, DM, DM);

    scan_k<<<dim3(HH * 2, BB, 2), 128>>>(rkv, rkv + TT * DM, rkv + 2 * TT * DM, decay, bonus);

    tsplit_k<<<dim3(DM / 32, DM / 32, 1), tb>>>(Wo, woh, wol, DM, DM);

    splitadd_k<<<(TT * DM + 255) / 256, 256>>>(yf, yb, yah, yal, TT * DM);

    // x1 = x + (yf+yb) @ Wo
    wgemm_k<1, 64><<<dim3(DM / BNw, TT / 64, 1), 256, GCfg<64>::SMEM>>>(
        yah, yal, woh, wol, x, x1, nullptr, nullptr, TT, DM, DM);

    rmsnorm_k<true><<<TT, 256>>>(x1, n2w, xn2, xn2h, xn2l);
    router_k<<<TT, 256>>>(xn2, rw);

    tsplit_k<<<dim3(DFFc / 32, DM / 32, EE), tb>>>(w1, w1h, w1l, DM, DFFc);

    // MoE up
    wgemm_k<2, 128><<<dim3(DFFc / BNw, TT / 128, EE), 256, GCfg<128>::SMEM>>>(
        xn2h, xn2l, w1h, w1l, nullptr, nullptr, hh, hl, 0, DFFc, DM);

    tsplit_k<<<dim3(DM / 32, DFFc / 32, EE), tb>>>(w2, w2h, w2l, DFFc, DM);

    // MoE down
    wgemm_k<3, 128><<<dim3(DM / BNw, TT / 128, EE), 256, GCfg<128>::SMEM>>>(
        hh, hl, w2h, w2l, nullptr, moe, nullptr, nullptr, 0, DM, DFFc);

    finalize_k<<<TT, 256>>>(out, out_size);
}